// round 1
// baseline (speedup 1.0000x reference)
#include <cuda_runtime.h>
#include <math.h>

#define QN 1000
#define KN 5
#define MN 50
#define DKN 64
#define DVN 128
#define DSN 50
#define BN 128
#define SN 2048

typedef unsigned long long ull;

// ---------- f32x2 helpers (sm_103a packed fp32 pipe) ----------
__device__ __forceinline__ ull ffma2(ull a, ull b, ull c) {
    ull d;
    asm("fma.rn.f32x2 %0, %1, %2, %3;" : "=l"(d) : "l"(a), "l"(b), "l"(c));
    return d;
}
__device__ __forceinline__ ull fpack2(float lo, float hi) {
    ull r;
    asm("mov.b64 %0, {%1, %2};" : "=l"(r) : "f"(lo), "f"(hi));
    return r;
}
__device__ __forceinline__ float2 funpack2(ull v) {
    float2 f;
    asm("mov.b64 {%0, %1}, %2;" : "=f"(f.x), "=f"(f.y) : "l"(v));
    return f;
}

// ---------- scratch (static device memory; no allocations allowed) ----------
__device__ float g_attn[QN * MN];            // softmax attention rows per question
__device__ float g_sq[QN * DSN];             // q_e part of summary + summary bias
__device__ float g_alphat[QN];               // softplus(q_e @ alpha_w + b)
__device__ float g_betat[QN * (KN - 1)];
__device__ float g_erase[QN * KN * DVN];     // sigmoid rows per (q,r) combo
__device__ float g_addt[QN * KN * DVN];      // tanh rows per (q,r) combo
__device__ float g_reads[(size_t)BN * SN * DVN];  // scan output (134 MB)

// ================= Kernel A: per-question tables =================
__global__ void k_qtab(const float* __restrict__ qe_w, const float* __restrict__ key_mem,
                       const float* __restrict__ sum_w, const float* __restrict__ sum_b,
                       const float* __restrict__ al_w, const float* __restrict__ al_b,
                       const float* __restrict__ be_w, const float* __restrict__ be_b) {
    int q = blockIdx.x, t = threadIdx.x;
    __shared__ float qe[DKN];
    __shared__ float sl[MN], se[MN];
    qe[t] = qe_w[q * DKN + t];
    __syncthreads();
    if (t < MN) {
        float acc = 0.f;
        #pragma unroll 8
        for (int k = 0; k < DKN; ++k) acc += qe[k] * key_mem[t * DKN + k];
        sl[t] = acc;
    }
    __syncthreads();
    if (t < MN) {
        float mx = -1e30f;
        for (int j = 0; j < MN; ++j) mx = fmaxf(mx, sl[j]);
        se[t] = expf(sl[t] - mx);
    }
    __syncthreads();
    if (t < MN) {
        float sm = 0.f;
        for (int j = 0; j < MN; ++j) sm += se[j];
        g_attn[q * MN + t] = se[t] / sm;
    }
    if (t < DSN) {
        float acc = sum_b[t];
        #pragma unroll 8
        for (int k = 0; k < DKN; ++k) acc += qe[k] * sum_w[(DVN + k) * DSN + t];
        g_sq[q * DSN + t] = acc;
    }
    if (t == 0) {
        float acc = al_b[0];
        for (int k = 0; k < DKN; ++k) acc += qe[k] * al_w[k];
        // numerically stable softplus == jnp.logaddexp(x, 0)
        g_alphat[q] = fmaxf(acc, 0.f) + log1pf(expf(-fabsf(acc)));
    }
    if (t < KN - 1) {
        float acc = be_b[t];
        for (int k = 0; k < DKN; ++k) acc += qe[k] * be_w[k * (KN - 1) + t];
        g_betat[q * (KN - 1) + t] = acc;
    }
}

// ================= Kernel B: per-(q,r) erase/add tables =================
__global__ void k_vtab(const float* __restrict__ item_w,
                       const float* __restrict__ vp_w, const float* __restrict__ vp_b,
                       const float* __restrict__ er_w, const float* __restrict__ er_b,
                       const float* __restrict__ ad_w, const float* __restrict__ ad_b) {
    int c = blockIdx.x;           // combo = q*K + r
    int q = c / KN, r = c % KN;
    int t = threadIdx.x;          // 128 threads, one per v
    __shared__ float item[DKN], rf[KN], ve[DVN];
    if (t < DKN) item[t] = item_w[q * DKN + t];
    if (t < KN)  rf[t] = fmaxf(1.f - fabsf((float)t - (float)r) * 0.25f, 0.f);
    __syncthreads();
    float acc = vp_b[t];
    #pragma unroll 8
    for (int k = 0; k < DKN; ++k) acc += item[k] * vp_w[k * DVN + t];
    #pragma unroll
    for (int j = 0; j < KN; ++j) acc += rf[j] * vp_w[(DKN + j) * DVN + t];
    ve[t] = acc;
    __syncthreads();
    float e = er_b[t], a = ad_b[t];
    #pragma unroll 8
    for (int k = 0; k < DVN; ++k) {
        float v = ve[k];
        e += v * er_w[k * DVN + t];
        a += v * ad_w[k * DVN + t];
    }
    g_erase[c * DVN + t] = 1.f / (1.f + expf(-e));
    g_addt[c * DVN + t]  = tanhf(a);
}

// ================= Kernel C: the sequential scan =================
// 128 CTAs (one per batch element). 128 threads = 64 v-pairs x 2 m-halves.
// Full memory state lives in registers as f32x2 pairs (25 per thread).
__global__ void __launch_bounds__(128, 1)
k_scan(const int* __restrict__ questions, const int* __restrict__ responses,
       const float* __restrict__ init_mem) {
    int b = blockIdx.x, tid = threadIdx.x;
    int vp = tid & 63;            // v-pair index: v = 2*vp, 2*vp+1
    int half = tid >> 6;          // m-half: [0,25) or [25,50)
    int m0 = half * 25;

    __shared__ int q_sh[SN];
    __shared__ unsigned char r_sh[SN];
    __shared__ float a_sh[2][MN];
    __shared__ __align__(8) float rp[2][128][2];

    for (int i = tid; i < SN; i += 128) {
        q_sh[i] = questions[b * SN + i];
        r_sh[i] = (unsigned char)responses[b * SN + i];
    }
    ull mem[25];
    #pragma unroll
    for (int i = 0; i < 25; ++i)
        mem[i] = *(const ull*)(init_mem + (m0 + i) * DVN + 2 * vp);
    __syncthreads();

    int q0 = q_sh[0];
    int c0 = q0 * KN + r_sh[0];
    if (tid < MN) a_sh[0][tid] = g_attn[q0 * MN + tid];
    ull e_cur  = *(const ull*)(g_erase + c0 * DVN + 2 * vp);
    ull ad_cur = *(const ull*)(g_addt + c0 * DVN + 2 * vp);
    __syncthreads();

    int buf = 0;
    float* outp = g_reads + (size_t)b * SN * DVN + 2 * vp;

    for (int t = 0; t < SN; ++t) {
        // prefetch step t+1 (L2-resident tables; latency hidden under compute)
        float a_nxt = 0.f;
        ull e_nxt = e_cur, ad_nxt = ad_cur;
        if (t + 1 < SN) {
            int qn = q_sh[t + 1];
            int cn = qn * KN + r_sh[t + 1];
            if (tid < MN) a_nxt = g_attn[qn * MN + tid];
            e_nxt  = *(const ull*)(g_erase + cn * DVN + 2 * vp);
            ad_nxt = *(const ull*)(g_addt + cn * DVN + 2 * vp);
        }

        // compute: read (pre-update) + memory update, all f32x2
        ull neg_e = e_cur ^ 0x8000000080000000ULL;   // negate both lanes
        ull r0 = 0ULL, r1 = 0ULL;
        #pragma unroll
        for (int i = 0; i < 25; ++i) {
            float a = a_sh[buf][m0 + i];             // broadcast LDS
            ull ap = fpack2(a, a);
            ull tmp = ffma2(neg_e, mem[i], ad_cur);  // add - e*mem
            if (i & 1) r1 = ffma2(ap, mem[i], r1);
            else       r0 = ffma2(ap, mem[i], r0);
            mem[i] = ffma2(ap, tmp, mem[i]);         // mem + a*(add - e*mem)
        }
        float2 fa = funpack2(r0), fb = funpack2(r1);
        rp[buf][tid][0] = fa.x + fb.x;
        rp[buf][tid][1] = fa.y + fb.y;
        if (tid < MN && t + 1 < SN) a_sh[buf ^ 1][tid] = a_nxt;
        __syncthreads();
        if (half == 0) {
            float ox = rp[buf][vp][0] + rp[buf][64 + vp][0];
            float oy = rp[buf][vp][1] + rp[buf][64 + vp][1];
            *(float2*)(outp + (size_t)t * DVN) = make_float2(ox, oy);
        }
        e_cur = e_nxt; ad_cur = ad_nxt; buf ^= 1;
    }
}

// ================= Kernel D: parallel epilogue =================
// One thread per (b,s). Ws_read (128x50) in smem, f32x2 accumulation.
__global__ void __launch_bounds__(256)
k_epi(const int* __restrict__ questions,
      const float* __restrict__ sum_w,
      const float* __restrict__ th_w, const float* __restrict__ th_b,
      float* __restrict__ out) {
    __shared__ __align__(8) float Ws[DVN * DSN];   // rows 0..127 of summary_w
    int tid = threadIdx.x;
    for (int i = tid; i < DVN * DSN; i += 256) Ws[i] = sum_w[i];
    __syncthreads();

    int task = blockIdx.x * 256 + tid;             // == b*S + s
    const float* rd = g_reads + (size_t)task * DVN;

    ull acc[25];
    #pragma unroll
    for (int j = 0; j < 25; ++j) acc[j] = 0ULL;
    #pragma unroll 2
    for (int v = 0; v < DVN; ++v) {
        float rv = __ldg(rd + v);
        ull rp2 = fpack2(rv, rv);
        const ull* wrow = (const ull*)(Ws + v * DSN);  // 200B row stride: 8B aligned
        #pragma unroll
        for (int j = 0; j < 25; ++j) acc[j] = ffma2(rp2, wrow[j], acc[j]);
    }

    int qid = questions[task];
    const float* sq = g_sq + qid * DSN;
    float th = th_b[0];
    #pragma unroll
    for (int j = 0; j < 25; ++j) {
        float2 ac = funpack2(acc[j]);
        float s0 = tanhf(ac.x + sq[2 * j]);
        float s1 = tanhf(ac.y + sq[2 * j + 1]);
        th += s0 * th_w[2 * j] + s1 * th_w[2 * j + 1];
    }
    float theta = tanhf(th);                       // ABILITY_SCALE = 1.0
    float alpha = g_alphat[qid];
    float inter = theta * alpha;
    float b0 = g_betat[qid * 4 + 0];
    float b1 = g_betat[qid * 4 + 1];
    float b2 = g_betat[qid * 4 + 2];
    float b3 = g_betat[qid * 4 + 3];

    float l0 = 0.f;
    float l1 = inter - b0;
    float l2 = l1 + inter - b1;
    float l3 = l2 + inter - b2;
    float l4 = l3 + inter - b3;

    float mx = fmaxf(fmaxf(fmaxf(l0, l1), fmaxf(l2, l3)), l4);
    float e0 = expf(l0 - mx), e1 = expf(l1 - mx), e2 = expf(l2 - mx);
    float e3 = expf(l3 - mx), e4 = expf(l4 - mx);
    float inv = 1.f / (e0 + e1 + e2 + e3 + e4);

    const int N = BN * SN;
    out[task] = theta;
    out[N + task] = alpha;
    float* bo = out + 2 * N + (size_t)task * 4;
    bo[0] = b0; bo[1] = b1; bo[2] = b2; bo[3] = b3;
    float* lo = out + 6 * N + (size_t)task * 5;
    lo[0] = l0; lo[1] = l1; lo[2] = l2; lo[3] = l3; lo[4] = l4;
    float* po = out + 11 * N + (size_t)task * 5;
    po[0] = e0 * inv; po[1] = e1 * inv; po[2] = e2 * inv;
    po[3] = e3 * inv; po[4] = e4 * inv;
}

// ================= launch =================
extern "C" void kernel_launch(void* const* d_in, const int* in_sizes, int n_in,
                              void* d_out, int out_size) {
    const int*   questions  = (const int*)d_in[0];
    const int*   responses  = (const int*)d_in[1];
    const float* q_embed_w  = (const float*)d_in[2];
    const float* item_w     = (const float*)d_in[3];
    const float* vp_w       = (const float*)d_in[4];
    const float* vp_b       = (const float*)d_in[5];
    const float* key_mem    = (const float*)d_in[6];
    const float* init_mem   = (const float*)d_in[7];
    const float* er_w       = (const float*)d_in[8];
    const float* er_b       = (const float*)d_in[9];
    const float* ad_w       = (const float*)d_in[10];
    const float* ad_b       = (const float*)d_in[11];
    const float* sum_w      = (const float*)d_in[12];
    const float* sum_b      = (const float*)d_in[13];
    const float* th_w       = (const float*)d_in[14];
    const float* th_b       = (const float*)d_in[15];
    const float* al_w       = (const float*)d_in[16];
    const float* al_b       = (const float*)d_in[17];
    const float* be_w       = (const float*)d_in[18];
    const float* be_b       = (const float*)d_in[19];
    float* out = (float*)d_out;

    k_qtab<<<QN, 64>>>(q_embed_w, key_mem, sum_w, sum_b, al_w, al_b, be_w, be_b);
    k_vtab<<<QN * KN, DVN>>>(item_w, vp_w, vp_b, er_w, er_b, ad_w, ad_b);
    k_scan<<<BN, 128>>>(questions, responses, init_mem);
    k_epi<<<(BN * SN) / 256, 256>>>(questions, sum_w, th_w, th_b, out);
}

// round 2
// speedup vs baseline: 1.6536x; 1.6536x over previous
#include <cuda_runtime.h>
#include <math.h>

#define QN 1000
#define KN 5
#define MN 50
#define DKN 64
#define DVN 128
#define DSN 50
#define BN 128
#define SN 2048

typedef unsigned long long ull;

// ---------- f32x2 helpers ----------
__device__ __forceinline__ ull ffma2(ull a, ull b, ull c) {
    ull d;
    asm("fma.rn.f32x2 %0, %1, %2, %3;" : "=l"(d) : "l"(a), "l"(b), "l"(c));
    return d;
}
__device__ __forceinline__ ull fpack2(float lo, float hi) {
    ull r;
    asm("mov.b64 %0, {%1, %2};" : "=l"(r) : "f"(lo), "f"(hi));
    return r;
}
__device__ __forceinline__ float2 funpack2(ull v) {
    float2 f;
    asm("mov.b64 {%0, %1}, %2;" : "=f"(f.x), "=f"(f.y) : "l"(v));
    return f;
}

// ---------- scratch ----------
__device__ float g_attn[QN * MN];
__device__ float g_sq[QN * DSN];
__device__ float g_alphat[QN];
__device__ float g_betat[QN * (KN - 1)];
__device__ float g_erase[QN * KN * DVN];
__device__ float g_addt[QN * KN * DVN];
__device__ float g_reads[(size_t)BN * SN * DVN];

// ================= Kernel A: per-question tables =================
__global__ void k_qtab(const float* __restrict__ qe_w, const float* __restrict__ key_mem,
                       const float* __restrict__ sum_w, const float* __restrict__ sum_b,
                       const float* __restrict__ al_w, const float* __restrict__ al_b,
                       const float* __restrict__ be_w, const float* __restrict__ be_b) {
    int q = blockIdx.x, t = threadIdx.x;
    __shared__ float qe[DKN];
    __shared__ float sl[MN], se[MN];
    qe[t] = qe_w[q * DKN + t];
    __syncthreads();
    if (t < MN) {
        float acc = 0.f;
        #pragma unroll 8
        for (int k = 0; k < DKN; ++k) acc += qe[k] * key_mem[t * DKN + k];
        sl[t] = acc;
    }
    __syncthreads();
    if (t < MN) {
        float mx = -1e30f;
        for (int j = 0; j < MN; ++j) mx = fmaxf(mx, sl[j]);
        se[t] = expf(sl[t] - mx);
    }
    __syncthreads();
    if (t < MN) {
        float sm = 0.f;
        for (int j = 0; j < MN; ++j) sm += se[j];
        g_attn[q * MN + t] = se[t] / sm;
    }
    if (t < DSN) {
        float acc = sum_b[t];
        #pragma unroll 8
        for (int k = 0; k < DKN; ++k) acc += qe[k] * sum_w[(DVN + k) * DSN + t];
        g_sq[q * DSN + t] = acc;
    }
    if (t == 0) {
        float acc = al_b[0];
        for (int k = 0; k < DKN; ++k) acc += qe[k] * al_w[k];
        g_alphat[q] = fmaxf(acc, 0.f) + log1pf(expf(-fabsf(acc)));
    }
    if (t < KN - 1) {
        float acc = be_b[t];
        for (int k = 0; k < DKN; ++k) acc += qe[k] * be_w[k * (KN - 1) + t];
        g_betat[q * (KN - 1) + t] = acc;
    }
}

// ================= Kernel B: per-(q,r) erase/add tables =================
__global__ void k_vtab(const float* __restrict__ item_w,
                       const float* __restrict__ vp_w, const float* __restrict__ vp_b,
                       const float* __restrict__ er_w, const float* __restrict__ er_b,
                       const float* __restrict__ ad_w, const float* __restrict__ ad_b) {
    int c = blockIdx.x;
    int q = c / KN, r = c % KN;
    int t = threadIdx.x;
    __shared__ float item[DKN], rf[KN], ve[DVN];
    if (t < DKN) item[t] = item_w[q * DKN + t];
    if (t < KN)  rf[t] = fmaxf(1.f - fabsf((float)t - (float)r) * 0.25f, 0.f);
    __syncthreads();
    float acc = vp_b[t];
    #pragma unroll 8
    for (int k = 0; k < DKN; ++k) acc += item[k] * vp_w[k * DVN + t];
    #pragma unroll
    for (int j = 0; j < KN; ++j) acc += rf[j] * vp_w[(DKN + j) * DVN + t];
    ve[t] = acc;
    __syncthreads();
    float e = er_b[t], a = ad_b[t];
    #pragma unroll 8
    for (int k = 0; k < DVN; ++k) {
        float v = ve[k];
        e += v * er_w[k * DVN + t];
        a += v * ad_w[k * DVN + t];
    }
    g_erase[c * DVN + t] = 1.f / (1.f + expf(-e));
    g_addt[c * DVN + t]  = tanhf(a);
}

// ================= Kernel C: sequential scan (v2) =================
// 128 CTAs (one per b), 256 threads = 8 warps.
// Warp owns 8 v-pairs (16 v). Lane = mg*8 + vsub: 4 m-groups of 13 m each
// (m = mg*13 + i, last group has 2 padding slots). Per-thread state: 13 f32x2
// memory elements. No block barriers in the loop; cross-mg reduction = shfl_xor.
// Full attention table (padded to 52 cols, zeros in 50/51) lives in dyn smem.
#define ATT_PAD 52
#define SCAN_SMEM (QN * ATT_PAD * 4 + SN * 4 + SN)

__global__ void __launch_bounds__(256, 1)
k_scan(const int* __restrict__ questions, const int* __restrict__ responses,
       const float* __restrict__ init_mem) {
    extern __shared__ char smem_raw[];
    float* attn_sh = (float*)smem_raw;                 // QN*52 floats
    int*   q_sh    = (int*)(smem_raw + QN * ATT_PAD * 4);
    unsigned char* r_sh = (unsigned char*)(q_sh + SN);

    int b = blockIdx.x, tid = threadIdx.x;
    int wid  = tid >> 5;
    int lane = tid & 31;
    int vsub = lane & 7;
    int mg   = lane >> 3;
    int vp   = wid * 8 + vsub;        // v-pair: v = 2vp, 2vp+1
    int mstart = mg * 13;

    // stage attention table (zero-padded columns 50,51)
    for (int idx = tid; idx < QN * ATT_PAD; idx += 256) {
        int q = idx / ATT_PAD, m = idx - q * ATT_PAD;
        attn_sh[idx] = (m < MN) ? g_attn[q * MN + m] : 0.f;
    }
    for (int i = tid; i < SN; i += 256) {
        q_sh[i] = questions[b * SN + i];
        r_sh[i] = (unsigned char)responses[b * SN + i];
    }

    ull mem[13];
    #pragma unroll
    for (int i = 0; i < 13; ++i) {
        int m = mstart + i;
        mem[i] = (m < MN) ? *(const ull*)(init_mem + m * DVN + 2 * vp) : 0ULL;
    }
    __syncthreads();

    // depth-2 prefetch pipeline for erase/add rows
    int c0 = q_sh[0] * KN + r_sh[0];
    int c1 = q_sh[1] * KN + r_sh[1];
    ull e0  = *(const ull*)(g_erase + c0 * DVN + 2 * vp);
    ull ad0 = *(const ull*)(g_addt  + c0 * DVN + 2 * vp);
    ull e1  = *(const ull*)(g_erase + c1 * DVN + 2 * vp);
    ull ad1 = *(const ull*)(g_addt  + c1 * DVN + 2 * vp);

    const float* abase = attn_sh + mstart;
    float* outp = g_reads + (size_t)b * SN * DVN + 2 * vp;

    #pragma unroll 2
    for (int t = 0; t < SN; ++t) {
        ull e_cur = e0, ad_cur = ad0;
        // rotate pipeline, issue load for t+2
        e0 = e1; ad0 = ad1;
        int tp = (t + 2 < SN) ? t + 2 : SN - 1;
        int cp = q_sh[tp] * KN + r_sh[tp];
        e1  = *(const ull*)(g_erase + cp * DVN + 2 * vp);
        ad1 = *(const ull*)(g_addt  + cp * DVN + 2 * vp);

        int qoff = q_sh[t] * ATT_PAD;
        ull neg_e = e_cur ^ 0x8000000080000000ULL;
        ull r0 = 0ULL, r1 = 0ULL;
        #pragma unroll
        for (int i = 0; i < 13; ++i) {
            float a = abase[qoff + i];               // broadcast LDS (0 for pad m)
            ull ap = fpack2(a, a);
            ull tmp = ffma2(neg_e, mem[i], ad_cur);  // add - e*mem
            if (i & 1) r1 = ffma2(ap, mem[i], r1);
            else       r0 = ffma2(ap, mem[i], r0);
            mem[i] = ffma2(ap, tmp, mem[i]);         // mem += a*(add - e*mem)
        }
        float2 fa = funpack2(r0), fb = funpack2(r1);
        float rx = fa.x + fb.x, ry = fa.y + fb.y;
        // reduce over the 4 m-groups (lane bits 3,4)
        rx += __shfl_xor_sync(0xffffffffu, rx, 8);
        ry += __shfl_xor_sync(0xffffffffu, ry, 8);
        rx += __shfl_xor_sync(0xffffffffu, rx, 16);
        ry += __shfl_xor_sync(0xffffffffu, ry, 16);
        if (mg == 0)
            *(float2*)(outp + (size_t)t * DVN) = make_float2(rx, ry);
    }
}

// ================= Kernel D: epilogue (v2, register-tiled) =================
// Block = 256 threads, tile = 128 tasks. reads tile staged in smem (coalesced
// float4 loads, padded stride 132), Ws staged as padded ull rows (stride 26).
// Thread = (tg, jq): 2 tasks (tg, tg+64) x 7 output-pairs (jq*7..jq*7+6).
#define TILE_T 128
#define R_STRIDE 132
#define W_STRIDE 26
#define EPI_SMEM (TILE_T * R_STRIDE * 4 + (DVN * W_STRIDE + 4) * 8)

__global__ void __launch_bounds__(256, 2)
k_epi(const int* __restrict__ questions,
      const float* __restrict__ sum_w,
      const float* __restrict__ th_w, const float* __restrict__ th_b,
      float* __restrict__ out) {
    extern __shared__ char smem_raw[];
    float* tileR = (float*)smem_raw;
    ull*   Wsu   = (ull*)(smem_raw + TILE_T * R_STRIDE * 4);
    float* Wsf   = (float*)Wsu;

    int tid = threadIdx.x;
    int t0 = blockIdx.x * TILE_T;

    // stage reads tile: coalesced float4
    for (int i = tid; i < TILE_T * (DVN / 4); i += 256) {
        int r = i >> 5, c4 = i & 31;
        float4 v = *(const float4*)(g_reads + (size_t)(t0 + r) * DVN + c4 * 4);
        *(float4*)(tileR + r * R_STRIDE + c4 * 4) = v;
    }
    // stage Ws (rows 0..127 of summary_w), zero-padded cols 50,51
    for (int i = tid; i < DVN * (2 * W_STRIDE); i += 256) {
        int v = i / (2 * W_STRIDE), j = i - v * (2 * W_STRIDE);
        Wsf[i] = (j < DSN) ? sum_w[v * DSN + j] : 0.f;
    }
    __syncthreads();

    int tg = tid >> 2;        // 0..63
    int jq = tid & 3;         // 0..3
    const float* rrow0 = tileR + tg * R_STRIDE;
    const float* rrow1 = tileR + (tg + 64) * R_STRIDE;
    const ull* wbase = Wsu + jq * 7;

    ull acc0[7], acc1[7];
    #pragma unroll
    for (int k = 0; k < 7; ++k) { acc0[k] = 0ULL; acc1[k] = 0ULL; }

    #pragma unroll 4
    for (int v = 0; v < DVN; ++v) {
        float rv0 = rrow0[v], rv1 = rrow1[v];
        ull rp0 = fpack2(rv0, rv0);
        ull rp1 = fpack2(rv1, rv1);
        const ull* w = wbase + v * W_STRIDE;
        #pragma unroll
        for (int k = 0; k < 7; ++k) {
            ull wv = w[k];
            acc0[k] = ffma2(rp0, wv, acc0[k]);
            acc1[k] = ffma2(rp1, wv, acc1[k]);
        }
    }

    float thb = th_b[0];
    const int N = BN * SN;

    #pragma unroll
    for (int which = 0; which < 2; ++which) {
        int task = t0 + tg + which * 64;
        ull* acc = which ? acc1 : acc0;
        int qid = questions[task];
        float thp = 0.f;
        #pragma unroll
        for (int k = 0; k < 7; ++k) {
            int p = jq * 7 + k;
            if (p < 25) {
                float2 ac = funpack2(acc[k]);
                float2 sq2 = funpack2(*(const ull*)(g_sq + qid * DSN + 2 * p));
                float2 tw  = funpack2(*(const ull*)(th_w + 2 * p));
                float s0 = tanhf(ac.x + sq2.x);
                float s1 = tanhf(ac.y + sq2.y);
                thp += s0 * tw.x + s1 * tw.y;
            }
        }
        thp += __shfl_xor_sync(0xffffffffu, thp, 1);
        thp += __shfl_xor_sync(0xffffffffu, thp, 2);
        if (jq == 0) {
            float theta = tanhf(thp + thb);
            float alpha = g_alphat[qid];
            float inter = theta * alpha;
            float b0 = g_betat[qid * 4 + 0];
            float b1 = g_betat[qid * 4 + 1];
            float b2 = g_betat[qid * 4 + 2];
            float b3 = g_betat[qid * 4 + 3];
            float l0 = 0.f;
            float l1 = inter - b0;
            float l2 = l1 + inter - b1;
            float l3 = l2 + inter - b2;
            float l4 = l3 + inter - b3;
            float mx = fmaxf(fmaxf(fmaxf(l0, l1), fmaxf(l2, l3)), l4);
            float e0x = expf(l0 - mx), e1x = expf(l1 - mx), e2x = expf(l2 - mx);
            float e3x = expf(l3 - mx), e4x = expf(l4 - mx);
            float inv = 1.f / (e0x + e1x + e2x + e3x + e4x);

            out[task] = theta;
            out[N + task] = alpha;
            float* bo = out + 2 * N + (size_t)task * 4;
            bo[0] = b0; bo[1] = b1; bo[2] = b2; bo[3] = b3;
            float* lo = out + 6 * N + (size_t)task * 5;
            lo[0] = l0; lo[1] = l1; lo[2] = l2; lo[3] = l3; lo[4] = l4;
            float* po = out + 11 * N + (size_t)task * 5;
            po[0] = e0x * inv; po[1] = e1x * inv; po[2] = e2x * inv;
            po[3] = e3x * inv; po[4] = e4x * inv;
        }
    }
}

// ================= launch =================
extern "C" void kernel_launch(void* const* d_in, const int* in_sizes, int n_in,
                              void* d_out, int out_size) {
    const int*   questions  = (const int*)d_in[0];
    const int*   responses  = (const int*)d_in[1];
    const float* q_embed_w  = (const float*)d_in[2];
    const float* item_w     = (const float*)d_in[3];
    const float* vp_w       = (const float*)d_in[4];
    const float* vp_b       = (const float*)d_in[5];
    const float* key_mem    = (const float*)d_in[6];
    const float* init_mem   = (const float*)d_in[7];
    const float* er_w       = (const float*)d_in[8];
    const float* er_b       = (const float*)d_in[9];
    const float* ad_w       = (const float*)d_in[10];
    const float* ad_b       = (const float*)d_in[11];
    const float* sum_w      = (const float*)d_in[12];
    const float* sum_b      = (const float*)d_in[13];
    const float* th_w       = (const float*)d_in[14];
    const float* th_b       = (const float*)d_in[15];
    const float* al_w       = (const float*)d_in[16];
    const float* al_b       = (const float*)d_in[17];
    const float* be_w       = (const float*)d_in[18];
    const float* be_b       = (const float*)d_in[19];
    float* out = (float*)d_out;

    static int configured = 0;
    if (!configured) {
        cudaFuncSetAttribute(k_scan, cudaFuncAttributeMaxDynamicSharedMemorySize, SCAN_SMEM);
        cudaFuncSetAttribute(k_epi,  cudaFuncAttributeMaxDynamicSharedMemorySize, EPI_SMEM);
        configured = 1;
    }

    k_qtab<<<QN, 64>>>(q_embed_w, key_mem, sum_w, sum_b, al_w, al_b, be_w, be_b);
    k_vtab<<<QN * KN, DVN>>>(item_w, vp_w, vp_b, er_w, er_b, ad_w, ad_b);
    k_scan<<<BN, 256, SCAN_SMEM>>>(questions, responses, init_mem);
    k_epi<<<(BN * SN) / TILE_T, 256, EPI_SMEM>>>(questions, sum_w, th_w, th_b, out);
}